// round 12
// baseline (speedup 1.0000x reference)
#include <cuda_runtime.h>
#include <math.h>
#include <stdint.h>

// Problem constants
#define B_   2
#define N_   3072
#define D_   320
#define H_   8
#define DH_  40
#define BH_  16
#define SCALE_ 0.15811388300841898f   // 40^-0.5

// ---------------- scratch (no allocation allowed) ----------------
__device__ float g_Q[BH_ * N_ * DH_];   // [bh, n, dh], pre-scaled, tf32-rounded
__device__ float g_K[BH_ * N_ * DH_];   // tf32-rounded
__device__ float g_V[BH_ * N_ * DH_];   // tf32-rounded
__device__ float g_O[B_ * N_ * D_];     // attention output, [b, n, h*40+c]
__device__ unsigned char g_M1[B_ * N_];
__device__ unsigned char g_M2[B_ * N_];

// ---------------- helpers ----------------
__device__ __forceinline__ float f2tf32(float x) {
    uint32_t u;
    asm("cvt.rna.tf32.f32 %0, %1;" : "=r"(u) : "f"(x));
    return __uint_as_float(u);
}

__device__ __forceinline__ void mma_tf32(
    float& d0, float& d1, float& d2, float& d3,
    float a0, float a1, float a2, float a3,
    float b0, float b1)
{
    asm volatile(
        "mma.sync.aligned.m16n8k8.row.col.f32.tf32.tf32.f32 "
        "{%0,%1,%2,%3}, {%4,%5,%6,%7}, {%8,%9}, {%0,%1,%2,%3};"
        : "+f"(d0), "+f"(d1), "+f"(d2), "+f"(d3)
        : "r"(__float_as_uint(a0)), "r"(__float_as_uint(a1)),
          "r"(__float_as_uint(a2)), "r"(__float_as_uint(a3)),
          "r"(__float_as_uint(b0)), "r"(__float_as_uint(b1)));
}

__device__ __forceinline__ void cpa16(uint32_t dst, const void* src) {
    asm volatile("cp.async.ca.shared.global [%0], [%1], 16;" :: "r"(dst), "l"(src));
}

// FFMA-pipe exp (no MUFU): e^s = 2^(s*log2e), |rel err| ~1e-5 for |s| < 80.
__device__ __forceinline__ float fexp(float s) {
    const float MAGIC = 12582912.0f;      // 2^23 + 2^22
    float y  = s * 1.4426950408889634f;
    float r  = y + MAGIC;
    int   i  = __float_as_int(r) - 0x4B400000;   // round(y) as int
    float fi = r - MAGIC;                         // round(y) as float
    float f  = y - fi;                            // f in [-0.5, 0.5]
    float p  = 0.0096181f;
    p = p * f + 0.0555041f;
    p = p * f + 0.2402265f;
    p = p * f + 0.6931472f;
    p = p * f + 1.0f;
    return __int_as_float(__float_as_int(p) + (i << 23));
}

// ---------------- mask kernel ----------------
__global__ void mask_kernel(const float* __restrict__ mask1,
                            const float* __restrict__ mask2) {
    int idx = blockIdx.x * 256 + threadIdx.x;
    if (idx >= B_ * N_) return;
    int b = idx / N_, i = idx - b * N_;
    int y = i / 48, x = i - y * 48;
    size_t src = ((size_t)b * 512 + (size_t)y * 8) * 384 + (size_t)x * 8;
    g_M1[idx] = (mask1[src] >= 0.5f) ? 1 : 0;
    g_M2[idx] = (mask2[src] >= 0.5f) ? 1 : 0;
}

// ---------------- tf32 tensor-core GEMM ----------------
// mode 0: QKV fused (blockIdx.z = 0/1/2 -> Q/K/V), scatter + tf32 round
// mode 3: A = g_O, dst = acc + bias
// Block tile 32x64, 4 warps (2x2), warp tile m16 x n32. Small blocks for
// occupancy: latency-bound regime per ncu (occ 18%, issue 34%).
#define TBM 32
#define TBN 64
#define TBK 16
#define ASL 20      // As [m][k] stride: banks (20g+t) mod 32 all distinct
#define WSL 72      // Ws [k][n] stride: banks (8t+g)  mod 32 all distinct
#define NKT (D_ / TBK)   // 20 k-tiles

__global__ __launch_bounds__(128) void gemm_tf32_kernel(
    const float* __restrict__ x, const float* __restrict__ ctx,
    const float* __restrict__ Wq, const float* __restrict__ Wk,
    const float* __restrict__ Wv, const float* __restrict__ bias,
    int mode, float* __restrict__ dst)
{
    __shared__ float As[2][TBM * ASL];
    __shared__ float Ws[2][TBK * WSL];

    const int z = blockIdx.z;
    const float* Ain;
    const float* W;
    float scale;
    if (mode == 3) { Ain = (const float*)g_O; W = Wq; scale = 1.f; }
    else {
        Ain = (z == 0) ? x : ctx;
        W = (z == 0) ? Wq : (z == 1) ? Wk : Wv;
        scale = (z == 0) ? SCALE_ : 1.f;
    }

    const int bm = blockIdx.y * TBM;
    const int bn = blockIdx.x * TBN;
    const int tid = threadIdx.x;
    const int w = tid >> 5, lane = tid & 31;
    const int g = lane >> 2, t = lane & 3;
    const int wm = (w & 1) * 16;
    const int wn = (w >> 1) * 32;

    float acc[4][4];
    #pragma unroll
    for (int ni = 0; ni < 4; ni++)
        #pragma unroll
        for (int r = 0; r < 4; r++) acc[ni][r] = 0.f;

    auto issue = [&](int k0, int bufi) {
        uint32_t abase = (uint32_t)__cvta_generic_to_shared(&As[bufi][0]);
        uint32_t wbase = (uint32_t)__cvta_generic_to_shared(&Ws[bufi][0]);
        {
            int r = tid >> 2, c = (tid & 3) * 4;     // A: 32 rows x 4 chunks
            cpa16(abase + (uint32_t)(r * ASL + c) * 4,
                  Ain + (size_t)(bm + r) * D_ + k0 + c);
        }
        #pragma unroll
        for (int i = 0; i < 2; i++) {
            int ch = tid * 2 + i;
            int r = ch >> 4, c = (ch & 15) * 4;      // W: 16 k-rows x 16 chunks
            cpa16(wbase + (uint32_t)(r * WSL + c) * 4,
                  W + (size_t)(k0 + r) * D_ + bn + c);
        }
    };

    issue(0, 0);
    asm volatile("cp.async.commit_group;");

    for (int kt = 0; kt < NKT; kt++) {
        int buf = kt & 1;
        if (kt + 1 < NKT) {
            issue((kt + 1) * TBK, buf ^ 1);
            asm volatile("cp.async.commit_group;");
            asm volatile("cp.async.wait_group 1;");
        } else {
            asm volatile("cp.async.wait_group 0;");
        }
        __syncthreads();

        const float* Ab = &As[buf][0];
        const float* Wb = &Ws[buf][0];

        #pragma unroll
        for (int kk = 0; kk < 2; kk++) {
            const int kb = kk * 8;
            const float* ar0 = Ab + (wm + g) * ASL + kb;
            const float* ar1 = Ab + (wm + g + 8) * ASL + kb;
            float a0 = f2tf32(ar0[t]);
            float a1 = f2tf32(ar1[t]);
            float a2 = f2tf32(ar0[t + 4]);
            float a3 = f2tf32(ar1[t + 4]);
            #pragma unroll
            for (int ni = 0; ni < 4; ni++) {
                float b0 = f2tf32(Wb[(kb + t) * WSL + wn + ni * 8 + g]);
                float b1 = f2tf32(Wb[(kb + t + 4) * WSL + wn + ni * 8 + g]);
                mma_tf32(acc[ni][0], acc[ni][1], acc[ni][2], acc[ni][3],
                         a0, a1, a2, a3, b0, b1);
            }
        }
        __syncthreads();
    }

    float* qkv = (z == 0) ? g_Q : (z == 1) ? g_K : g_V;
    int r0 = bm + wm + g;
    int r1 = r0 + 8;
    #pragma unroll
    for (int ni = 0; ni < 4; ni++) {
        int col = bn + wn + ni * 8 + 2 * t;
        if (mode == 3) {
            float2 bb = *(const float2*)&bias[col];
            *(float2*)&dst[(size_t)r0 * D_ + col] =
                make_float2(acc[ni][0] + bb.x, acc[ni][1] + bb.y);
            *(float2*)&dst[(size_t)r1 * D_ + col] =
                make_float2(acc[ni][2] + bb.x, acc[ni][3] + bb.y);
        } else {
            int h = col / DH_, c = col - h * DH_;
            int b0r = r0 / N_, n0r = r0 - b0r * N_;
            int b1r = r1 / N_, n1r = r1 - b1r * N_;
            *(float2*)&qkv[(((size_t)(b0r * H_ + h)) * N_ + n0r) * DH_ + c] =
                make_float2(f2tf32(acc[ni][0] * scale),
                            f2tf32(acc[ni][1] * scale));
            *(float2*)&qkv[(((size_t)(b1r * H_ + h)) * N_ + n1r) * DH_ + c] =
                make_float2(f2tf32(acc[ni][2] * scale),
                            f2tf32(acc[ni][3] * scale));
        }
    }
}

// ---------------- tensor-core flash attention (tf32 mma) ----------------
// 32 query rows per warp, 4 warps = 128 queries/block. 3-stage cp.async
// pipeline with a SINGLE __syncthreads per key-tile.
#define KT 32
#define KS 44
#define VS 40
#define PS 36
#define NT (N_ / KT)   // 96 tiles

__global__ __launch_bounds__(128) void attn_kernel() {
    __shared__ float Ksm[3][KT * KS];
    __shared__ float Vsm[3][KT * VS];
    __shared__ float Psm[4][32 * PS];
    __shared__ unsigned char m2s[3][KT];

    const int bh = blockIdx.y;
    const int b  = bh >> 3;
    const int h  = bh & 7;
    const int tid  = threadIdx.x;
    const int w    = tid >> 5;
    const int lane = tid & 31;
    const int g = lane >> 2;
    const int t = lane & 3;
    const int q0 = blockIdx.x * 128 + w * 32;

    const float* Qb = g_Q + (size_t)bh * N_ * DH_;
    const float* Kb = g_K + (size_t)bh * N_ * DH_;
    const float* Vb = g_V + (size_t)bh * N_ * DH_;
    const unsigned char* M2b = g_M2 + b * N_;

    float aq[2][5][4];
    bool m1f[2][2];
    #pragma unroll
    for (int mi = 0; mi < 2; mi++) {
        const float* qr0 = Qb + (size_t)(q0 + mi * 16 + g) * DH_;
        const float* qr1 = Qb + (size_t)(q0 + mi * 16 + g + 8) * DH_;
        #pragma unroll
        for (int ks = 0; ks < 5; ks++) {
            aq[mi][ks][0] = qr0[8 * ks + t];
            aq[mi][ks][1] = qr1[8 * ks + t];
            aq[mi][ks][2] = qr0[8 * ks + t + 4];
            aq[mi][ks][3] = qr1[8 * ks + t + 4];
        }
        m1f[mi][0] = g_M1[b * N_ + q0 + mi * 16 + g] != 0;
        m1f[mi][1] = g_M1[b * N_ + q0 + mi * 16 + g + 8] != 0;
    }

    float o[2][5][4];
    float l[2][2];
    #pragma unroll
    for (int mi = 0; mi < 2; mi++) {
        l[mi][0] = 0.f; l[mi][1] = 0.f;
        #pragma unroll
        for (int i = 0; i < 5; i++)
            #pragma unroll
            for (int r = 0; r < 4; r++) o[mi][i][r] = 0.f;
    }

    auto issue = [&](int tile, int bufi) {
        const float* Ksrc = Kb + (size_t)tile * KT * DH_;
        const float4* vg = (const float4*)(Vb + (size_t)tile * KT * DH_);
        uint32_t kdst = (uint32_t)__cvta_generic_to_shared(&Ksm[bufi][0]);
        uint32_t vdst = (uint32_t)__cvta_generic_to_shared(&Vsm[bufi][0]);
        #pragma unroll
        for (int i = 0; i < 3; i++) {
            int c = tid + i * 128;
            if (c < 320) {
                int key = c / 10, f4 = c - key * 10;
                cpa16(kdst + (uint32_t)(key * KS + f4 * 4) * 4,
                      Ksrc + key * DH_ + f4 * 4);
                cpa16(vdst + (uint32_t)c * 16, vg + c);   // dense: VS == DH_
            }
        }
        if (tid < 2) {
            uint32_t mdst = (uint32_t)__cvta_generic_to_shared(&m2s[bufi][0]);
            cpa16(mdst + tid * 16, M2b + tile * KT + tid * 16);
        }
    };

    issue(0, 0);
    asm volatile("cp.async.commit_group;");
    issue(1, 1);
    asm volatile("cp.async.commit_group;");

    for (int tile = 0; tile < NT; tile++) {
        int buf = tile - (tile / 3) * 3;
        if (tile == NT - 1) {
            asm volatile("cp.async.wait_group 0;");
        } else {
            asm volatile("cp.async.wait_group 1;");
        }
        __syncthreads();   // also proves all warps finished tile-1's compute
        if (tile + 2 < NT) {
            int nb2 = (tile + 2) - ((tile + 2) / 3) * 3;
            issue(tile + 2, nb2);
            asm volatile("cp.async.commit_group;");
        }

        const float* Kt = &Ksm[buf][0];
        const float* Vt = &Vsm[buf][0];
        float* Pw = &Psm[w][0];

        // ---- scores: S[32,32] = Q @ K^T; K fragments reused across mi
        #pragma unroll
        for (int nb = 0; nb < 4; nb++) {
            float bfr[5][2];
            const float* krow = Kt + (nb * 8 + g) * KS;
            #pragma unroll
            for (int ks = 0; ks < 5; ks++) {
                bfr[ks][0] = krow[8 * ks + t];
                bfr[ks][1] = krow[8 * ks + 4 + t];
            }
            bool mc0 = m2s[buf][nb * 8 + 2 * t] != 0;
            bool mc1 = m2s[buf][nb * 8 + 2 * t + 1] != 0;
            #pragma unroll
            for (int mi = 0; mi < 2; mi++) {
                float d0 = 0.f, d1 = 0.f, d2 = 0.f, d3 = 0.f;
                #pragma unroll
                for (int ks = 0; ks < 5; ks++)
                    mma_tf32(d0, d1, d2, d3,
                             aq[mi][ks][0], aq[mi][ks][1],
                             aq[mi][ks][2], aq[mi][ks][3],
                             bfr[ks][0], bfr[ks][1]);
                float p0 = (m1f[mi][0] && mc0) ? 0.f : fexp(d0);
                float p1 = (m1f[mi][0] && mc1) ? 0.f : fexp(d1);
                float p2 = (m1f[mi][1] && mc0) ? 0.f : fexp(d2);
                float p3 = (m1f[mi][1] && mc1) ? 0.f : fexp(d3);
                l[mi][0] += p0 + p1;
                l[mi][1] += p2 + p3;
                *(float2*)&Pw[(mi * 16 + g) * PS + nb * 8 + 2 * t] =
                    make_float2(f2tf32(p0), f2tf32(p1));
                *(float2*)&Pw[(mi * 16 + g + 8) * PS + nb * 8 + 2 * t] =
                    make_float2(f2tf32(p2), f2tf32(p3));
            }
        }
        __syncwarp();

        // ---- O += P @ V; V fragments reused across mi
        #pragma unroll
        for (int kb = 0; kb < 4; kb++) {
            float bv[5][2];
            const float* vr0 = Vt + (kb * 8 + t) * VS;
            const float* vr1 = Vt + (kb * 8 + t + 4) * VS;
            #pragma unroll
            for (int nbo = 0; nbo < 5; nbo++) {
                bv[nbo][0] = vr0[nbo * 8 + g];
                bv[nbo][1] = vr1[nbo * 8 + g];
            }
            #pragma unroll
            for (int mi = 0; mi < 2; mi++) {
                float a0 = Pw[(mi * 16 + g) * PS + kb * 8 + t];
                float a1 = Pw[(mi * 16 + g + 8) * PS + kb * 8 + t];
                float a2 = Pw[(mi * 16 + g) * PS + kb * 8 + t + 4];
                float a3 = Pw[(mi * 16 + g + 8) * PS + kb * 8 + t + 4];
                #pragma unroll
                for (int nbo = 0; nbo < 5; nbo++)
                    mma_tf32(o[mi][nbo][0], o[mi][nbo][1],
                             o[mi][nbo][2], o[mi][nbo][3],
                             a0, a1, a2, a3, bv[nbo][0], bv[nbo][1]);
            }
        }
        __syncwarp();
    }

    // ---- reduce row sums across quads, normalize, write
    #pragma unroll
    for (int mi = 0; mi < 2; mi++) {
        l[mi][0] += __shfl_xor_sync(0xffffffffu, l[mi][0], 1);
        l[mi][0] += __shfl_xor_sync(0xffffffffu, l[mi][0], 2);
        l[mi][1] += __shfl_xor_sync(0xffffffffu, l[mi][1], 1);
        l[mi][1] += __shfl_xor_sync(0xffffffffu, l[mi][1], 2);

        float inv0, inv1;
        if (l[mi][0] > 0.f) {
            inv0 = 1.f / l[mi][0];
        } else {
            #pragma unroll
            for (int nbo = 0; nbo < 5; nbo++) { o[mi][nbo][0] = 0.f; o[mi][nbo][1] = 0.f; }
            for (int j = 0; j < N_; j++) {
                const float* vr = Vb + (size_t)j * DH_;
                #pragma unroll
                for (int nbo = 0; nbo < 5; nbo++) {
                    o[mi][nbo][0] += vr[nbo * 8 + 2 * t];
                    o[mi][nbo][1] += vr[nbo * 8 + 2 * t + 1];
                }
            }
            inv0 = 1.f / (float)N_;
        }
        if (l[mi][1] > 0.f) {
            inv1 = 1.f / l[mi][1];
        } else {
            #pragma unroll
            for (int nbo = 0; nbo < 5; nbo++) { o[mi][nbo][2] = 0.f; o[mi][nbo][3] = 0.f; }
            for (int j = 0; j < N_; j++) {
                const float* vr = Vb + (size_t)j * DH_;
                #pragma unroll
                for (int nbo = 0; nbo < 5; nbo++) {
                    o[mi][nbo][2] += vr[nbo * 8 + 2 * t];
                    o[mi][nbo][3] += vr[nbo * 8 + 2 * t + 1];
                }
            }
            inv1 = 1.f / (float)N_;
        }

        float* O0 = g_O + (size_t)(b * N_ + q0 + mi * 16 + g) * D_ + h * DH_;
        float* O1 = g_O + (size_t)(b * N_ + q0 + mi * 16 + g + 8) * D_ + h * DH_;
        #pragma unroll
        for (int nbo = 0; nbo < 5; nbo++) {
            *(float2*)&O0[nbo * 8 + 2 * t] =
                make_float2(o[mi][nbo][0] * inv0, o[mi][nbo][1] * inv0);
            *(float2*)&O1[nbo * 8 + 2 * t] =
                make_float2(o[mi][nbo][2] * inv1, o[mi][nbo][3] * inv1);
        }
    }
}

// ---------------- launch ----------------
extern "C" void kernel_launch(void* const* d_in, const int* in_sizes, int n_in,
                              void* d_out, int out_size) {
    (void)in_sizes; (void)n_in; (void)out_size;
    const float* x     = (const float*)d_in[0];
    const float* ctx   = (const float*)d_in[1];
    const float* mask1 = (const float*)d_in[2];
    const float* mask2 = (const float*)d_in[3];
    const float* Wq    = (const float*)d_in[4];
    const float* Wk    = (const float*)d_in[5];
    const float* Wv    = (const float*)d_in[6];
    const float* Wo    = (const float*)d_in[7];
    const float* bo    = (const float*)d_in[8];
    float* out = (float*)d_out;

    dim3 gqkv(D_ / TBN, (B_ * N_) / TBM, 3);   // (5, 192, 3)
    dim3 gout(D_ / TBN, (B_ * N_) / TBM, 1);   // (5, 192, 1)

    mask_kernel<<<(B_ * N_ + 255) / 256, 256>>>(mask1, mask2);
    gemm_tf32_kernel<<<gqkv, 128>>>(x, ctx, Wq, Wk, Wv, nullptr, 0, nullptr);
    attn_kernel<<<dim3(N_ / 128, BH_), 128>>>();
    gemm_tf32_kernel<<<gout, 128>>>(nullptr, nullptr, Wo, nullptr, nullptr, bo, 3, out);
}

// round 13
// speedup vs baseline: 1.2527x; 1.2527x over previous
#include <cuda_runtime.h>
#include <math.h>
#include <stdint.h>

// Problem constants
#define B_   2
#define N_   3072
#define D_   320
#define H_   8
#define DH_  40
#define BH_  16
#define SCALE_ 0.15811388300841898f   // 40^-0.5

// ---------------- scratch (no allocation allowed) ----------------
__device__ float g_Q[BH_ * N_ * DH_];    // [bh, n, dh], pre-scaled, tf32-rounded
__device__ float g_K[BH_ * N_ * DH_];    // tf32-rounded
__device__ float g_V[BH_ * N_ * DH_];    // tf32-rounded
__device__ float g_O[B_ * N_ * D_];      // attention out, tf32-rounded
__device__ float g_x[B_ * N_ * D_];      // tf32-rounded copy of x
__device__ float g_c[B_ * N_ * D_];      // tf32-rounded copy of context
__device__ float g_W[4][D_ * D_];        // tf32-rounded Wq,Wk,Wv,Wo
__device__ unsigned char g_M1[B_ * N_];
__device__ unsigned char g_M2[B_ * N_];

// ---------------- helpers ----------------
__device__ __forceinline__ float f2tf32(float x) {
    uint32_t u;
    asm("cvt.rna.tf32.f32 %0, %1;" : "=r"(u) : "f"(x));
    return __uint_as_float(u);
}

__device__ __forceinline__ void mma_tf32(
    float& d0, float& d1, float& d2, float& d3,
    float a0, float a1, float a2, float a3,
    float b0, float b1)
{
    asm volatile(
        "mma.sync.aligned.m16n8k8.row.col.f32.tf32.tf32.f32 "
        "{%0,%1,%2,%3}, {%4,%5,%6,%7}, {%8,%9}, {%0,%1,%2,%3};"
        : "+f"(d0), "+f"(d1), "+f"(d2), "+f"(d3)
        : "r"(__float_as_uint(a0)), "r"(__float_as_uint(a1)),
          "r"(__float_as_uint(a2)), "r"(__float_as_uint(a3)),
          "r"(__float_as_uint(b0)), "r"(__float_as_uint(b1)));
}

__device__ __forceinline__ void cpa16(uint32_t dst, const void* src) {
    asm volatile("cp.async.ca.shared.global [%0], [%1], 16;" :: "r"(dst), "l"(src));
}

// ---------------- pre-round pass: tf32-round x, ctx, W into scratch --------
#define XE (B_ * N_ * D_)       // 1966080 elems
#define WE (D_ * D_)            // 102400 elems
#define PRE_TOT ((2 * XE + 4 * WE) / 4)   // float4 count = 1085440

__global__ void preround_kernel(const float* __restrict__ x,
                                const float* __restrict__ ctx,
                                const float* __restrict__ Wq,
                                const float* __restrict__ Wk,
                                const float* __restrict__ Wv,
                                const float* __restrict__ Wo) {
    int i = blockIdx.x * 256 + threadIdx.x;
    if (i >= PRE_TOT) return;
    const float4* src;
    float4* dst;
    int j = i;
    if (j < XE / 4)            { src = (const float4*)x;   dst = (float4*)g_x; }
    else if ((j -= XE / 4) < XE / 4) { src = (const float4*)ctx; dst = (float4*)g_c; }
    else if ((j -= XE / 4) < WE / 4) { src = (const float4*)Wq;  dst = (float4*)g_W[0]; }
    else if ((j -= WE / 4) < WE / 4) { src = (const float4*)Wk;  dst = (float4*)g_W[1]; }
    else if ((j -= WE / 4) < WE / 4) { src = (const float4*)Wv;  dst = (float4*)g_W[2]; }
    else { j -= WE / 4;          src = (const float4*)Wo;  dst = (float4*)g_W[3]; }
    float4 v = src[j];
    v.x = f2tf32(v.x); v.y = f2tf32(v.y); v.z = f2tf32(v.z); v.w = f2tf32(v.w);
    dst[j] = v;
}

// ---------------- mask kernel ----------------
__global__ void mask_kernel(const float* __restrict__ mask1,
                            const float* __restrict__ mask2) {
    int idx = blockIdx.x * 256 + threadIdx.x;
    if (idx >= B_ * N_) return;
    int b = idx / N_, i = idx - b * N_;
    int y = i / 48, x = i - y * 48;
    size_t src = ((size_t)b * 512 + (size_t)y * 8) * 384 + (size_t)x * 8;
    g_M1[idx] = (mask1[src] >= 0.5f) ? 1 : 0;
    g_M2[idx] = (mask2[src] >= 0.5f) ? 1 : 0;
}

// ---------------- tf32 tensor-core GEMM (all operands pre-rounded) ---------
// mode 0: QKV fused (blockIdx.z = 0/1/2 -> Q/K/V), scatter + tf32 round
// mode 3: A = g_O, dst = acc + bias
#define TBM 64
#define TBN 64
#define TBK 16
#define ASL 20      // As [m][k] stride: banks (20g+t) mod 32 all distinct
#define WSL 72      // Ws [k][n] stride: banks (8t+g)  mod 32 all distinct
#define NKT (D_ / TBK)   // 20 k-tiles

__global__ __launch_bounds__(128) void gemm_tf32_kernel(
    const float* __restrict__ bias, int mode, float* __restrict__ dst)
{
    __shared__ float As[2][TBM * ASL];
    __shared__ float Ws[2][TBK * WSL];

    const int z = blockIdx.z;
    const float* Ain;
    const float* W;
    float scale;
    if (mode == 3) { Ain = (const float*)g_O; W = g_W[3]; scale = 1.f; }
    else {
        Ain = (z == 0) ? g_x : g_c;
        W = g_W[z];
        scale = (z == 0) ? SCALE_ : 1.f;
    }

    const int bm = blockIdx.y * TBM;
    const int bn = blockIdx.x * TBN;
    const int tid = threadIdx.x;
    const int w = tid >> 5, lane = tid & 31;
    const int g = lane >> 2, t = lane & 3;
    const int wm = (w & 1) * 32;
    const int wn = (w >> 1) * 32;

    float acc[2][4][4];
    #pragma unroll
    for (int mi = 0; mi < 2; mi++)
        #pragma unroll
        for (int ni = 0; ni < 4; ni++)
            #pragma unroll
            for (int r = 0; r < 4; r++) acc[mi][ni][r] = 0.f;

    auto issue = [&](int k0, int bufi) {
        uint32_t abase = (uint32_t)__cvta_generic_to_shared(&As[bufi][0]);
        uint32_t wbase = (uint32_t)__cvta_generic_to_shared(&Ws[bufi][0]);
        #pragma unroll
        for (int i = 0; i < 2; i++) {
            int ch = tid * 2 + i;
            int r = ch >> 2, c = (ch & 3) * 4;
            cpa16(abase + (uint32_t)(r * ASL + c) * 4,
                  Ain + (size_t)(bm + r) * D_ + k0 + c);
        }
        #pragma unroll
        for (int i = 0; i < 2; i++) {
            int ch = tid * 2 + i;
            int r = ch >> 4, c = (ch & 15) * 4;
            cpa16(wbase + (uint32_t)(r * WSL + c) * 4,
                  W + (size_t)(k0 + r) * D_ + bn + c);
        }
    };

    issue(0, 0);
    asm volatile("cp.async.commit_group;");

    for (int kt = 0; kt < NKT; kt++) {
        int buf = kt & 1;
        if (kt + 1 < NKT) {
            issue((kt + 1) * TBK, buf ^ 1);
            asm volatile("cp.async.commit_group;");
            asm volatile("cp.async.wait_group 1;");
        } else {
            asm volatile("cp.async.wait_group 0;");
        }
        __syncthreads();

        const float* Ab = &As[buf][0];
        const float* Wb = &Ws[buf][0];

        #pragma unroll
        for (int kk = 0; kk < 2; kk++) {
            const int kb = kk * 8;
            float a[2][4];
            #pragma unroll
            for (int mi = 0; mi < 2; mi++) {
                const float* ar0 = Ab + (wm + mi * 16 + g) * ASL + kb;
                const float* ar1 = Ab + (wm + mi * 16 + g + 8) * ASL + kb;
                a[mi][0] = ar0[t];
                a[mi][1] = ar1[t];
                a[mi][2] = ar0[t + 4];
                a[mi][3] = ar1[t + 4];
            }
            float bf[4][2];
            #pragma unroll
            for (int ni = 0; ni < 4; ni++) {
                bf[ni][0] = Wb[(kb + t) * WSL + wn + ni * 8 + g];
                bf[ni][1] = Wb[(kb + t + 4) * WSL + wn + ni * 8 + g];
            }
            #pragma unroll
            for (int mi = 0; mi < 2; mi++)
                #pragma unroll
                for (int ni = 0; ni < 4; ni++)
                    mma_tf32(acc[mi][ni][0], acc[mi][ni][1],
                             acc[mi][ni][2], acc[mi][ni][3],
                             a[mi][0], a[mi][1], a[mi][2], a[mi][3],
                             bf[ni][0], bf[ni][1]);
        }
        __syncthreads();
    }

    float* qkv = (z == 0) ? g_Q : (z == 1) ? g_K : g_V;
    #pragma unroll
    for (int mi = 0; mi < 2; mi++) {
        int r0 = bm + wm + mi * 16 + g;
        int r1 = r0 + 8;
        #pragma unroll
        for (int ni = 0; ni < 4; ni++) {
            int col = bn + wn + ni * 8 + 2 * t;
            if (mode == 3) {
                float2 bb = *(const float2*)&bias[col];
                *(float2*)&dst[(size_t)r0 * D_ + col] =
                    make_float2(acc[mi][ni][0] + bb.x, acc[mi][ni][1] + bb.y);
                *(float2*)&dst[(size_t)r1 * D_ + col] =
                    make_float2(acc[mi][ni][2] + bb.x, acc[mi][ni][3] + bb.y);
            } else {
                int h = col / DH_, c = col - h * DH_;
                int b0r = r0 / N_, n0r = r0 - b0r * N_;
                int b1r = r1 / N_, n1r = r1 - b1r * N_;
                *(float2*)&qkv[(((size_t)(b0r * H_ + h)) * N_ + n0r) * DH_ + c] =
                    make_float2(f2tf32(acc[mi][ni][0] * scale),
                                f2tf32(acc[mi][ni][1] * scale));
                *(float2*)&qkv[(((size_t)(b1r * H_ + h)) * N_ + n1r) * DH_ + c] =
                    make_float2(f2tf32(acc[mi][ni][2] * scale),
                                f2tf32(acc[mi][ni][3] * scale));
            }
        }
    }
}

// ---------------- tensor-core flash attention (tf32 mma) ----------------
// 32 query rows per warp (two m16 groups share every K/V B-fragment),
// 4 warps = 128 queries per block. K stride 44 (rows indexed by g),
// V dense stride 40 (rows indexed by t) -> both conflict-free.
#define KT 32
#define KS 44
#define VS 40
#define PS 36
#define NT (N_ / KT)   // 96 tiles

__global__ __launch_bounds__(128) void attn_kernel() {
    __shared__ float Ksm[2][KT * KS];
    __shared__ float Vsm[2][KT * VS];
    __shared__ float Psm[4][32 * PS];
    __shared__ unsigned char m2s[2][KT];

    const int bh = blockIdx.y;
    const int b  = bh >> 3;
    const int h  = bh & 7;
    const int tid  = threadIdx.x;
    const int w    = tid >> 5;
    const int lane = tid & 31;
    const int g = lane >> 2;
    const int t = lane & 3;
    const int q0 = blockIdx.x * 128 + w * 32;

    const float* Qb = g_Q + (size_t)bh * N_ * DH_;
    const float* Kb = g_K + (size_t)bh * N_ * DH_;
    const float* Vb = g_V + (size_t)bh * N_ * DH_;
    const unsigned char* M2b = g_M2 + b * N_;

    float aq[2][5][4];
    bool m1f[2][2];
    #pragma unroll
    for (int mi = 0; mi < 2; mi++) {
        const float* qr0 = Qb + (size_t)(q0 + mi * 16 + g) * DH_;
        const float* qr1 = Qb + (size_t)(q0 + mi * 16 + g + 8) * DH_;
        #pragma unroll
        for (int ks = 0; ks < 5; ks++) {
            aq[mi][ks][0] = qr0[8 * ks + t];
            aq[mi][ks][1] = qr1[8 * ks + t];
            aq[mi][ks][2] = qr0[8 * ks + t + 4];
            aq[mi][ks][3] = qr1[8 * ks + t + 4];
        }
        m1f[mi][0] = g_M1[b * N_ + q0 + mi * 16 + g] != 0;
        m1f[mi][1] = g_M1[b * N_ + q0 + mi * 16 + g + 8] != 0;
    }

    float o[2][5][4];
    float l[2][2];
    #pragma unroll
    for (int mi = 0; mi < 2; mi++) {
        l[mi][0] = 0.f; l[mi][1] = 0.f;
        #pragma unroll
        for (int i = 0; i < 5; i++)
            #pragma unroll
            for (int r = 0; r < 4; r++) o[mi][i][r] = 0.f;
    }

    auto issue = [&](int tile, int bufi) {
        const float* Ksrc = Kb + (size_t)tile * KT * DH_;
        const float4* vg = (const float4*)(Vb + (size_t)tile * KT * DH_);
        uint32_t kdst = (uint32_t)__cvta_generic_to_shared(&Ksm[bufi][0]);
        uint32_t vdst = (uint32_t)__cvta_generic_to_shared(&Vsm[bufi][0]);
        #pragma unroll
        for (int i = 0; i < 3; i++) {
            int c = tid + i * 128;
            if (c < 320) {
                int key = c / 10, f4 = c - key * 10;
                cpa16(kdst + (uint32_t)(key * KS + f4 * 4) * 4,
                      Ksrc + key * DH_ + f4 * 4);
                cpa16(vdst + (uint32_t)c * 16, vg + c);   // dense: VS == DH_
            }
        }
        if (tid < 2) {
            uint32_t mdst = (uint32_t)__cvta_generic_to_shared(&m2s[bufi][0]);
            cpa16(mdst + tid * 16, M2b + tile * KT + tid * 16);
        }
    };

    issue(0, 0);
    asm volatile("cp.async.commit_group;");

    for (int tile = 0; tile < NT; tile++) {
        int buf = tile & 1;
        if (tile + 1 < NT) {
            issue(tile + 1, buf ^ 1);
            asm volatile("cp.async.commit_group;");
            asm volatile("cp.async.wait_group 1;");
        } else {
            asm volatile("cp.async.wait_group 0;");
        }
        __syncthreads();

        const float* Kt = &Ksm[buf][0];
        const float* Vt = &Vsm[buf][0];
        float* Pw = &Psm[w][0];

        // ---- scores: S[32,32] = Q @ K^T; K fragments reused across mi
        #pragma unroll
        for (int nb = 0; nb < 4; nb++) {
            float bfr[5][2];
            const float* krow = Kt + (nb * 8 + g) * KS;
            #pragma unroll
            for (int ks = 0; ks < 5; ks++) {
                bfr[ks][0] = krow[8 * ks + t];
                bfr[ks][1] = krow[8 * ks + 4 + t];
            }
            bool mc0 = m2s[buf][nb * 8 + 2 * t] != 0;
            bool mc1 = m2s[buf][nb * 8 + 2 * t + 1] != 0;
            #pragma unroll
            for (int mi = 0; mi < 2; mi++) {
                float d0 = 0.f, d1 = 0.f, d2 = 0.f, d3 = 0.f;
                #pragma unroll
                for (int ks = 0; ks < 5; ks++)
                    mma_tf32(d0, d1, d2, d3,
                             aq[mi][ks][0], aq[mi][ks][1],
                             aq[mi][ks][2], aq[mi][ks][3],
                             bfr[ks][0], bfr[ks][1]);
                float p0 = (m1f[mi][0] && mc0) ? 0.f : __expf(d0);
                float p1 = (m1f[mi][0] && mc1) ? 0.f : __expf(d1);
                float p2 = (m1f[mi][1] && mc0) ? 0.f : __expf(d2);
                float p3 = (m1f[mi][1] && mc1) ? 0.f : __expf(d3);
                l[mi][0] += p0 + p1;
                l[mi][1] += p2 + p3;
                *(float2*)&Pw[(mi * 16 + g) * PS + nb * 8 + 2 * t] =
                    make_float2(f2tf32(p0), f2tf32(p1));
                *(float2*)&Pw[(mi * 16 + g + 8) * PS + nb * 8 + 2 * t] =
                    make_float2(f2tf32(p2), f2tf32(p3));
            }
        }
        __syncwarp();

        // ---- O += P @ V; V fragments reused across mi
        #pragma unroll
        for (int kb = 0; kb < 4; kb++) {
            float bv[5][2];
            const float* vr0 = Vt + (kb * 8 + t) * VS;
            const float* vr1 = Vt + (kb * 8 + t + 4) * VS;
            #pragma unroll
            for (int nbo = 0; nbo < 5; nbo++) {
                bv[nbo][0] = vr0[nbo * 8 + g];
                bv[nbo][1] = vr1[nbo * 8 + g];
            }
            #pragma unroll
            for (int mi = 0; mi < 2; mi++) {
                float a0 = Pw[(mi * 16 + g) * PS + kb * 8 + t];
                float a1 = Pw[(mi * 16 + g + 8) * PS + kb * 8 + t];
                float a2 = Pw[(mi * 16 + g) * PS + kb * 8 + t + 4];
                float a3 = Pw[(mi * 16 + g + 8) * PS + kb * 8 + t + 4];
                #pragma unroll
                for (int nbo = 0; nbo < 5; nbo++)
                    mma_tf32(o[mi][nbo][0], o[mi][nbo][1],
                             o[mi][nbo][2], o[mi][nbo][3],
                             a0, a1, a2, a3, bv[nbo][0], bv[nbo][1]);
            }
        }
        __syncwarp();
        __syncthreads();
    }

    // ---- reduce row sums across quads, normalize, write (tf32-rounded)
    #pragma unroll
    for (int mi = 0; mi < 2; mi++) {
        l[mi][0] += __shfl_xor_sync(0xffffffffu, l[mi][0], 1);
        l[mi][0] += __shfl_xor_sync(0xffffffffu, l[mi][0], 2);
        l[mi][1] += __shfl_xor_sync(0xffffffffu, l[mi][1], 1);
        l[mi][1] += __shfl_xor_sync(0xffffffffu, l[mi][1], 2);

        float inv0, inv1;
        if (l[mi][0] > 0.f) {
            inv0 = 1.f / l[mi][0];
        } else {
            #pragma unroll
            for (int nbo = 0; nbo < 5; nbo++) { o[mi][nbo][0] = 0.f; o[mi][nbo][1] = 0.f; }
            for (int j = 0; j < N_; j++) {
                const float* vr = Vb + (size_t)j * DH_;
                #pragma unroll
                for (int nbo = 0; nbo < 5; nbo++) {
                    o[mi][nbo][0] += vr[nbo * 8 + 2 * t];
                    o[mi][nbo][1] += vr[nbo * 8 + 2 * t + 1];
                }
            }
            inv0 = 1.f / (float)N_;
        }
        if (l[mi][1] > 0.f) {
            inv1 = 1.f / l[mi][1];
        } else {
            #pragma unroll
            for (int nbo = 0; nbo < 5; nbo++) { o[mi][nbo][2] = 0.f; o[mi][nbo][3] = 0.f; }
            for (int j = 0; j < N_; j++) {
                const float* vr = Vb + (size_t)j * DH_;
                #pragma unroll
                for (int nbo = 0; nbo < 5; nbo++) {
                    o[mi][nbo][2] += vr[nbo * 8 + 2 * t];
                    o[mi][nbo][3] += vr[nbo * 8 + 2 * t + 1];
                }
            }
            inv1 = 1.f / (float)N_;
        }

        float* O0 = g_O + (size_t)(b * N_ + q0 + mi * 16 + g) * D_ + h * DH_;
        float* O1 = g_O + (size_t)(b * N_ + q0 + mi * 16 + g + 8) * D_ + h * DH_;
        #pragma unroll
        for (int nbo = 0; nbo < 5; nbo++) {
            *(float2*)&O0[nbo * 8 + 2 * t] =
                make_float2(f2tf32(o[mi][nbo][0] * inv0), f2tf32(o[mi][nbo][1] * inv0));
            *(float2*)&O1[nbo * 8 + 2 * t] =
                make_float2(f2tf32(o[mi][nbo][2] * inv1), f2tf32(o[mi][nbo][3] * inv1));
        }
    }
}

// ---------------- launch ----------------
extern "C" void kernel_launch(void* const* d_in, const int* in_sizes, int n_in,
                              void* d_out, int out_size) {
    (void)in_sizes; (void)n_in; (void)out_size;
    const float* x     = (const float*)d_in[0];
    const float* ctx   = (const float*)d_in[1];
    const float* mask1 = (const float*)d_in[2];
    const float* mask2 = (const float*)d_in[3];
    const float* Wq    = (const float*)d_in[4];
    const float* Wk    = (const float*)d_in[5];
    const float* Wv    = (const float*)d_in[6];
    const float* Wo    = (const float*)d_in[7];
    const float* bo    = (const float*)d_in[8];
    float* out = (float*)d_out;

    dim3 gqkv(D_ / TBN, (B_ * N_) / TBM, 3);   // (5, 96, 3)
    dim3 gout(D_ / TBN, (B_ * N_) / TBM, 1);

    preround_kernel<<<(PRE_TOT + 255) / 256, 256>>>(x, ctx, Wq, Wk, Wv, Wo);
    mask_kernel<<<(B_ * N_ + 255) / 256, 256>>>(mask1, mask2);
    gemm_tf32_kernel<<<gqkv, 128>>>(nullptr, 0, nullptr);
    attn_kernel<<<dim3(N_ / 128, BH_), 128>>>();
    gemm_tf32_kernel<<<gout, 128>>>(bo, 3, out);
}